// round 6
// baseline (speedup 1.0000x reference)
#include <cuda_runtime.h>
#include <cuda_bf16.h>
#include <cstdint>
#include <math.h>

// ---------------- problem constants ----------------
#define C_DIM   256
#define M_CLS   256
#define HW      16384
#define N_PIX   262144
#define TILE_P  128
#define KB      32                    // channels per A chunk
#define NKS     (C_DIM / KB)          // 8
#define NBLOCKS (N_PIX / TILE_P)      // 2048
#define NTHREADS 1024
#define INV_T   14.2857142857142857f  // 1/0.07

// ---------------- smem layout (bytes) ----------------
#define SM_B    0
#define B_BYTES (M_CLS * C_DIM * 2)        // 131072
#define SM_A0   (B_BYTES)                  // 131072
#define SM_A1   (SM_A0 + TILE_P * KB * 2)  // 139264
#define SM_RED  (SM_A1 + TILE_P * KB * 2)  // 147456: sn[8][128], sp[8][128], wpart[8]
#define SMEM_BYTES (SM_RED + 8192 + 64)    // 155712

__device__ float2 g_partials[NBLOCKS];
__device__ __align__(16) __nv_bfloat16 g_queue_bf[M_CLS * C_DIM];
__device__ unsigned int g_done;   // zero-init; reset by last block each launch

__device__ __forceinline__ uint32_t smem_u32(const void* p) {
    uint32_t a;
    asm("{ .reg .u64 t; cvta.to.shared.u64 t, %1; cvt.u32.u64 %0, t; }" : "=r"(a) : "l"(p));
    return a;
}
__device__ __forceinline__ uint32_t pkbf2(float x, float y) {
    __nv_bfloat162 h = __floats2bfloat162_rn(x, y);
    return *(uint32_t*)&h;
}
#define CP_ASYNC16(dst, src) \
    asm volatile("cp.async.cg.shared.global [%0], [%1], 16;" :: "r"(dst), "l"(src) : "memory")
#define CP_COMMIT()  asm volatile("cp.async.commit_group;" ::: "memory")
#define CP_WAIT0()   asm volatile("cp.async.wait_group 0;" ::: "memory")

#define LDMATRIX_X4(r0, r1, r2, r3, addr) \
    asm volatile("ldmatrix.sync.aligned.m8n8.x4.shared.b16 {%0,%1,%2,%3}, [%4];" \
                 : "=r"(r0), "=r"(r1), "=r"(r2), "=r"(r3) : "r"(addr))

#define MMA16816(c, a0, a1, a2, a3, b0, b1) \
    asm volatile("mma.sync.aligned.m16n8k16.row.col.f32.bf16.bf16.f32 " \
                 "{%0,%1,%2,%3}, {%4,%5,%6,%7}, {%8,%9}, {%0,%1,%2,%3};" \
                 : "+f"((c)[0]), "+f"((c)[1]), "+f"((c)[2]), "+f"((c)[3]) \
                 : "r"(a0), "r"(a1), "r"(a2), "r"(a3), "r"(b0), "r"(b1))

// ---- pre-pass: queue f32 -> bf16 (once per launch) ----
__global__ void queue_to_bf16_kernel(const float* __restrict__ queue)
{
    int i = (blockIdx.x * blockDim.x + threadIdx.x) * 2;
    float2 v = *(const float2*)(queue + i);
    __nv_bfloat162 b;
    b.x = __float2bfloat16(v.x);
    b.y = __float2bfloat16(v.y);
    *(__nv_bfloat162*)(g_queue_bf + i) = b;
}

__global__ __launch_bounds__(NTHREADS, 1)
void pcl_hmma_kernel(const float* __restrict__ feats,
                     const int*   __restrict__ labels,
                     float*       __restrict__ out)
{
    extern __shared__ char smem[];
    const uint32_t sb   = smem_u32(smem);
    const int tid  = threadIdx.x;
    const int warp = tid >> 5;
    const int lane = tid & 31;
    const int pix0 = blockIdx.x * TILE_P;

    // feats [b,c,h,w]; TILE_P divides HW so a CTA never crosses an image
    const float* fbase = feats + (size_t)(pix0 / HW) * C_DIM * HW + (pix0 % HW);

    // ---- B staging: whole 128KB queue via cp.async, class-permuted + swizzled ----
    // Permutation inside each 32-class group: physical p5 = 8t+2ni+e is stored at
    // logical slot 8ni+2t+e, so one thread's epilogue classes are 8 CONTIGUOUS
    // physical classes (int4-pair label loads).
    {
        #pragma unroll
        for (int i = 0; i < 8; i++) {
            int q    = tid + NTHREADS * i;       // 0..8191 16B-chunks
            int cls  = q >> 5;                   // physical class
            int c    = q & 31;
            int p5   = cls & 31;
            int slot = ((p5 & 6) << 2) | ((p5 >> 3) << 1) | (p5 & 1);
            int lrow = (cls & ~31) | slot;       // logical smem row
            uint32_t dst = sb + SM_B + lrow * 512 + ((c ^ (lrow & 7)) << 4);
            const void* src = (const char*)g_queue_bf + cls * 512 + c * 16;
            CP_ASYNC16(dst, src);
        }
        CP_COMMIT();
    }

    // ---- A staging roles: thread = (chg 0..7, pixA 0..127), 4 channels each ----
    const int pixA = tid & 127;
    const int chg  = tid >> 7;
    const uint32_t a_st_off = pixA * 64 +
        ((((uint32_t)(chg >> 1)) ^ ((pixA >> 1) & 3)) << 4) + (chg & 1) * 8;

    float areg[4];
    auto loadA = [&](int ks) {
        #pragma unroll
        for (int j = 0; j < 4; j++)
            areg[j] = __ldg(fbase + (size_t)(ks * KB + chg * 4 + j) * HW + pixA);
    };
    auto storeA = [&](uint32_t abase) {
        uint32_t w0 = pkbf2(areg[0], areg[1]);
        uint32_t w1 = pkbf2(areg[2], areg[3]);
        asm volatile("st.shared.v2.b32 [%0], {%1,%2};"
                     :: "r"(abase + a_st_off), "r"(w0), "r"(w1) : "memory");
    };

    loadA(0);
    storeA(sb + SM_A0);
    CP_WAIT0();
    __syncthreads();

    // ---- warp tiling: 32 warps = 4(pix) x 8(cls); warp tile 32 pix x 32 cls ----
    const int wm = warp & 3;     // pixel coord -> rows wm*32..+31
    const int wn = warp >> 2;    // class coord -> cols wn*32..+31

    // A ldmatrix lane addressing
    const int arow0 = wm * 32 + (lane & 15);
    const int ksel  = lane >> 4;
    const uint32_t a_ld_base[2] = { (uint32_t)(arow0 * 64),
                                    (uint32_t)((arow0 + 16) * 64) };
    const uint32_t a_swz[2] = { (uint32_t)((arow0 >> 1) & 3),
                                (uint32_t)(((arow0 + 16) >> 1) & 3) };

    // B ldmatrix lane addressing (logical rows)
    const int bg   = lane & 7;
    const int bsel = lane >> 3;                       // 0..3
    const int bofs = bg + ((bsel >= 2) ? 8 : 0);
    const int bkh  = bsel & 1;

    float acc[2][4][4];
    #pragma unroll
    for (int mi = 0; mi < 2; mi++)
        #pragma unroll
        for (int ni = 0; ni < 4; ni++)
            #pragma unroll
            for (int r = 0; r < 4; r++) acc[mi][ni][r] = 0.0f;

    // ---- mainloop: 8 chunks of 32 channels, double-buffered A ----
    #pragma unroll 1
    for (int ks = 0; ks < NKS; ks++) {
        if (ks < NKS - 1) loadA(ks + 1);

        const uint32_t acur = sb + ((ks & 1) ? SM_A1 : SM_A0);
        #pragma unroll
        for (int kf = 0; kf < 2; kf++) {
            uint32_t afr[2][4];
            #pragma unroll
            for (int mi = 0; mi < 2; mi++) {
                uint32_t addr = acur + a_ld_base[mi] +
                                (((uint32_t)(kf * 2 + ksel) ^ a_swz[mi]) << 4);
                LDMATRIX_X4(afr[mi][0], afr[mi][1], afr[mi][2], afr[mi][3], addr);
            }
            const uint32_t kchunk = ks * 4 + kf * 2 + bkh;
            #pragma unroll
            for (int nt = 0; nt < 2; nt++) {
                const int lcls = wn * 32 + nt * 16 + bofs;
                uint32_t b0, b1, b2, b3;
                uint32_t addr = sb + SM_B + lcls * 512 + ((kchunk ^ (uint32_t)(lcls & 7)) << 4);
                LDMATRIX_X4(b0, b1, b2, b3, addr);
                #pragma unroll
                for (int mi = 0; mi < 2; mi++) {
                    MMA16816(acc[mi][nt * 2 + 0], afr[mi][0], afr[mi][1], afr[mi][2], afr[mi][3], b0, b1);
                    MMA16816(acc[mi][nt * 2 + 1], afr[mi][0], afr[mi][1], afr[mi][2], afr[mi][3], b2, b3);
                }
            }
        }

        if (ks < NKS - 1) {
            storeA(sb + (((ks + 1) & 1) ? SM_A1 : SM_A0));
            __syncthreads();
        }
    }

    // ---- register epilogue ----
    // acc logical n (in warp tile) = ni*8 + 2t + e  <->  physical class offset
    // (after permutation) = t*8 + 2ni + e, so thread t's labels are the 8
    // contiguous physical classes [wn*32 + t*8, +8) -> two int4 loads.
    const int g = lane >> 2;
    const int t = lane & 3;
    float* red_sn = (float*)(smem + SM_RED);            // [8][128]
    float* red_sp = (float*)(smem + SM_RED + 4096);     // [8][128]
    float* wpart  = (float*)(smem + SM_RED + 8192);     // [8]

    #pragma unroll
    for (int mi = 0; mi < 2; mi++) {
        #pragma unroll
        for (int h = 0; h < 2; h++) {
            const int pixel = wm * 32 + mi * 16 + h * 8 + g;
            const int4* lp = (const int4*)(labels + (size_t)(pix0 + pixel) * M_CLS + wn * 32 + t * 8);
            int4 la = __ldg(lp);
            int4 lb = __ldg(lp + 1);
            int l[8] = { la.x, la.y, la.z, la.w, lb.x, lb.y, lb.z, lb.w };
            float sn = 0.0f, sp = 0.0f;
            #pragma unroll
            for (int ni = 0; ni < 4; ni++) {
                #pragma unroll
                for (int e = 0; e < 2; e++) {
                    int   lv = l[2 * ni + e];
                    float v  = acc[mi][ni][h * 2 + e] * INV_T;
                    float ev = __expf(lv ? -v : v);
                    if (lv) sp += ev; else sn += ev;
                }
            }
            sn += __shfl_xor_sync(0xFFFFFFFFu, sn, 1);
            sn += __shfl_xor_sync(0xFFFFFFFFu, sn, 2);
            sp += __shfl_xor_sync(0xFFFFFFFFu, sp, 1);
            sp += __shfl_xor_sync(0xFFFFFFFFu, sp, 2);
            if (t == 0) {
                red_sn[wn * 128 + pixel] = sn;
                red_sp[wn * 128 + pixel] = sp;
            }
        }
    }
    __syncthreads();

    // ---- combine 8 class-slices per pixel, loss, block reduction ----
    float th_loss = 0.0f, th_cnt = 0.0f;
    if (tid < 128) {
        float tsn = 0.0f, tsp = 0.0f;
        #pragma unroll
        for (int s = 0; s < 8; s++) {
            tsn += red_sn[s * 128 + tid];
            tsp += red_sp[s * 128 + tid];
        }
        float loss = logf(tsn * tsp + 1.0f);
        th_loss = loss;
        th_cnt  = (loss != 0.0f) ? 1.0f : 0.0f;
        #pragma unroll
        for (int o = 16; o > 0; o >>= 1) {
            th_loss += __shfl_xor_sync(0xFFFFFFFFu, th_loss, o);
            th_cnt  += __shfl_xor_sync(0xFFFFFFFFu, th_cnt,  o);
        }
        if (lane == 0) { wpart[warp] = th_loss; wpart[warp + 4] = th_cnt; }
    }
    __syncthreads();

    __shared__ bool is_last;
    if (tid == 0) {
        float s = wpart[0] + wpart[1] + wpart[2] + wpart[3];
        float c = wpart[4] + wpart[5] + wpart[6] + wpart[7];
        g_partials[blockIdx.x] = make_float2(s, c);
        __threadfence();
        unsigned old = atomicAdd(&g_done, 1u);
        is_last = (old == NBLOCKS - 1);
    }
    __syncthreads();

    // ---- last arriving block: deterministic final reduction (reuse dead B smem) ----
    if (is_last) {
        double* dsum = (double*)(smem);          // 8KB
        float*  fcnt = (float*)(smem + 8192);    // 4KB
        double s = 0.0;
        float  c = 0.0f;
        #pragma unroll
        for (int it = 0; it < NBLOCKS / NTHREADS; it++) {
            float2 p = g_partials[tid + it * NTHREADS];
            s += (double)p.x;
            c += p.y;
        }
        dsum[tid] = s;
        fcnt[tid] = c;
        __syncthreads();
        for (int o = NTHREADS / 2; o > 0; o >>= 1) {
            if (tid < o) { dsum[tid] += dsum[tid + o]; fcnt[tid] += fcnt[tid + o]; }
            __syncthreads();
        }
        if (tid == 0) {
            float cnt = fcnt[0];
            out[0] = (cnt == 0.0f) ? 0.0f : (float)(dsum[0] / (double)fmaxf(cnt, 1.0f));
            __threadfence();
            g_done = 0;
        }
    }
}

extern "C" void kernel_launch(void* const* d_in, const int* in_sizes, int n_in,
                              void* d_out, int out_size)
{
    // metadata.txt order: feats (f32), queue (f32), labels (i32).
    // feats and labels have identical element counts — positional ID only.
    const float* feats  = (const float*)d_in[0];
    const float* queue  = (const float*)d_in[1];
    const int*   labels = (const int*)d_in[2];

    cudaFuncSetAttribute(pcl_hmma_kernel,
                         cudaFuncAttributeMaxDynamicSharedMemorySize, SMEM_BYTES);

    queue_to_bf16_kernel<<<M_CLS * C_DIM / (2 * 256), 256>>>(queue);
    pcl_hmma_kernel<<<NBLOCKS, NTHREADS, SMEM_BYTES>>>(feats, labels, (float*)d_out);
}

// round 7
// speedup vs baseline: 1.4190x; 1.4190x over previous
#include <cuda_runtime.h>
#include <cuda_bf16.h>
#include <cstdint>
#include <math.h>

// ---------------- problem constants ----------------
#define C_DIM   256
#define M_CLS   256
#define HW      16384
#define N_PIX   262144
#define TILE_P  128
#define KB      32                    // channels per A chunk
#define NKS     (C_DIM / KB)          // 8
#define NBLOCKS (N_PIX / TILE_P)      // 2048
#define NTHREADS 512
#define GRID    152                   // persistent: one CTA per SM (GB300 = 152 SMs)
#define INV_T   14.2857142857142857f  // 1/0.07

// ---------------- smem layout (bytes) ----------------
#define SM_B    0
#define B_BYTES (M_CLS * C_DIM * 2)        // 131072
#define SM_A0   (B_BYTES)                  // 131072
#define SM_A1   (SM_A0 + TILE_P * KB * 2)  // 139264
#define SM_RED  (SM_A1 + TILE_P * KB * 2)  // 147456: sn[4][128], sp[4][128], wpart[8]
#define SMEM_BYTES (SM_RED + 4096 + 64)    // 151616

__device__ double g_sum[GRID];
__device__ float  g_cnt[GRID];
__device__ __align__(16) __nv_bfloat16 g_queue_bf[M_CLS * C_DIM];
__device__ unsigned int g_done;   // zero-init; reset by last CTA each launch

__device__ __forceinline__ uint32_t smem_u32(const void* p) {
    uint32_t a;
    asm("{ .reg .u64 t; cvta.to.shared.u64 t, %1; cvt.u32.u64 %0, t; }" : "=r"(a) : "l"(p));
    return a;
}
__device__ __forceinline__ uint32_t pkbf2(float x, float y) {
    __nv_bfloat162 h = __floats2bfloat162_rn(x, y);
    return *(uint32_t*)&h;
}
#define CP_ASYNC16(dst, src) \
    asm volatile("cp.async.cg.shared.global [%0], [%1], 16;" :: "r"(dst), "l"(src) : "memory")
#define CP_COMMIT()  asm volatile("cp.async.commit_group;" ::: "memory")
#define CP_WAIT0()   asm volatile("cp.async.wait_group 0;" ::: "memory")

#define LDMATRIX_X4(r0, r1, r2, r3, addr) \
    asm volatile("ldmatrix.sync.aligned.m8n8.x4.shared.b16 {%0,%1,%2,%3}, [%4];" \
                 : "=r"(r0), "=r"(r1), "=r"(r2), "=r"(r3) : "r"(addr))

#define MMA16816(c, a0, a1, a2, a3, b0, b1) \
    asm volatile("mma.sync.aligned.m16n8k16.row.col.f32.bf16.bf16.f32 " \
                 "{%0,%1,%2,%3}, {%4,%5,%6,%7}, {%8,%9}, {%0,%1,%2,%3};" \
                 : "+f"((c)[0]), "+f"((c)[1]), "+f"((c)[2]), "+f"((c)[3]) \
                 : "r"(a0), "r"(a1), "r"(a2), "r"(a3), "r"(b0), "r"(b1))

// ---- pre-pass: queue f32 -> bf16 (once per launch) ----
__global__ void queue_to_bf16_kernel(const float* __restrict__ queue)
{
    int i = (blockIdx.x * blockDim.x + threadIdx.x) * 2;
    float2 v = *(const float2*)(queue + i);
    __nv_bfloat162 b;
    b.x = __float2bfloat16(v.x);
    b.y = __float2bfloat16(v.y);
    *(__nv_bfloat162*)(g_queue_bf + i) = b;
}

__global__ __launch_bounds__(NTHREADS, 1)
void pcl_persist_kernel(const float* __restrict__ feats,
                        const int*   __restrict__ labels,
                        float*       __restrict__ out)
{
    extern __shared__ char smem[];
    const uint32_t sb   = smem_u32(smem);
    const int tid  = threadIdx.x;
    const int warp = tid >> 5;
    const int lane = tid & 31;

    // ---- B staging ONCE: 128KB queue via cp.async, class-permuted + swizzled ----
    // Within each 64-class group: physical p6 = 16t + 2ni + e is stored at logical
    // slot 8ni + 2t + e, so a thread's 16 epilogue classes are physically
    // contiguous [wn*64 + 16t, +16) -> 4 int4 label loads.
    {
        #pragma unroll
        for (int i = 0; i < 16; i++) {
            int q    = tid + NTHREADS * i;       // 0..8191 16B-chunks
            int cls  = q >> 5;                   // physical class
            int c    = q & 31;
            int p6   = cls & 63;
            int slot = (((p6 >> 1) & 7) << 3) | (((p6 >> 4) & 3) << 1) | (p6 & 1);
            int lrow = (cls & ~63) | slot;       // logical smem row
            uint32_t dst = sb + SM_B + lrow * 512 + ((c ^ (lrow & 7)) << 4);
            const void* src = (const char*)g_queue_bf + cls * 512 + c * 16;
            CP_ASYNC16(dst, src);
        }
        CP_COMMIT();
    }

    // ---- A staging roles: thread = (chg 0..3, pixA 0..127), 8 channels each ----
    const int pixA = tid & 127;
    const int chg  = tid >> 7;
    const uint32_t a_st_off = pixA * 64 + ((chg ^ ((pixA >> 1) & 3)) << 4);

    float areg[8];
    auto loadA = [&](const float* fb, int ks) {
        #pragma unroll
        for (int j = 0; j < 8; j++)
            areg[j] = __ldg(fb + (size_t)(ks * KB + chg * 8 + j) * HW + pixA);
    };
    auto storeA = [&](uint32_t abase) {
        uint4 w;
        w.x = pkbf2(areg[0], areg[1]);
        w.y = pkbf2(areg[2], areg[3]);
        w.z = pkbf2(areg[4], areg[5]);
        w.w = pkbf2(areg[6], areg[7]);
        asm volatile("st.shared.v4.b32 [%0], {%1,%2,%3,%4};"
                     :: "r"(abase + a_st_off), "r"(w.x), "r"(w.y), "r"(w.z), "r"(w.w) : "memory");
    };

    // ---- warp tiling: 16 warps = 4(pix) x 4(cls); warp tile 32 pix x 64 cls ----
    const int wm = warp & 3;
    const int wn = warp >> 2;

    const int arow0 = wm * 32 + (lane & 15);
    const int ksel  = lane >> 4;
    const uint32_t a_ld_base[2] = { (uint32_t)(arow0 * 64),
                                    (uint32_t)((arow0 + 16) * 64) };
    const uint32_t a_swz[2] = { (uint32_t)((arow0 >> 1) & 3),
                                (uint32_t)(((arow0 + 16) >> 1) & 3) };

    const int bg   = lane & 7;
    const int bsel = lane >> 3;
    const int bofs = bg + ((bsel >= 2) ? 8 : 0);
    const int bkh  = bsel & 1;

    const int g = lane >> 2;
    const int t = lane & 3;
    float* red_sn = (float*)(smem + SM_RED);            // [4][128]
    float* red_sp = (float*)(smem + SM_RED + 2048);     // [4][128]
    float* wpart  = (float*)(smem + SM_RED + 4096);     // [8]

    double acc_s = 0.0;   // per-CTA loss accumulator (thread 0)
    float  acc_c = 0.0f;

    // ---- prologue for first tile ----
    int tile = blockIdx.x;
    const float* fbase = feats + (size_t)((tile * TILE_P) / HW) * C_DIM * HW
                               + ((tile * TILE_P) % HW);
    loadA(fbase, 0);
    storeA(sb + SM_A0);
    CP_WAIT0();
    __syncthreads();

    // ---- persistent tile loop ----
    #pragma unroll 1
    for (; tile < NBLOCKS; tile += GRID) {
        const int pix0 = tile * TILE_P;
        const int next_tile = tile + GRID;
        const float* fbase_next =
            (next_tile < NBLOCKS)
                ? feats + (size_t)((next_tile * TILE_P) / HW) * C_DIM * HW
                        + ((next_tile * TILE_P) % HW)
                : fbase;

        float acc[2][8][4];
        #pragma unroll
        for (int mi = 0; mi < 2; mi++)
            #pragma unroll
            for (int ni = 0; ni < 8; ni++)
                #pragma unroll
                for (int r = 0; r < 4; r++) acc[mi][ni][r] = 0.0f;

        // ---- mainloop: 8 chunks, double-buffered A, cross-tile prefetch ----
        #pragma unroll 1
        for (int ks = 0; ks < NKS; ks++) {
            const bool have_next = (ks < NKS - 1) || (next_tile < NBLOCKS);
            if (ks < NKS - 1)           loadA(fbase, ks + 1);
            else if (have_next)         loadA(fbase_next, 0);

            const uint32_t acur = sb + ((ks & 1) ? SM_A1 : SM_A0);
            #pragma unroll
            for (int kf = 0; kf < 2; kf++) {
                uint32_t afr[2][4];
                #pragma unroll
                for (int mi = 0; mi < 2; mi++) {
                    uint32_t addr = acur + a_ld_base[mi] +
                                    (((uint32_t)(kf * 2 + ksel) ^ a_swz[mi]) << 4);
                    LDMATRIX_X4(afr[mi][0], afr[mi][1], afr[mi][2], afr[mi][3], addr);
                }
                const uint32_t kchunk = ks * 4 + kf * 2 + bkh;
                #pragma unroll
                for (int nt = 0; nt < 4; nt++) {
                    const int lcls = wn * 64 + nt * 16 + bofs;
                    uint32_t b0, b1, b2, b3;
                    uint32_t addr = sb + SM_B + lcls * 512 +
                                    ((kchunk ^ (uint32_t)(lcls & 7)) << 4);
                    LDMATRIX_X4(b0, b1, b2, b3, addr);
                    #pragma unroll
                    for (int mi = 0; mi < 2; mi++) {
                        MMA16816(acc[mi][nt * 2 + 0], afr[mi][0], afr[mi][1], afr[mi][2], afr[mi][3], b0, b1);
                        MMA16816(acc[mi][nt * 2 + 1], afr[mi][0], afr[mi][1], afr[mi][2], afr[mi][3], b2, b3);
                    }
                }
            }

            if (have_next) {
                storeA(sb + (((ks + 1) & 1) ? SM_A1 : SM_A0));
                __syncthreads();
            }
        }

        // ---- register epilogue: permuted labels -> 4 int4 loads per (mi,h) ----
        // acc[mi][ni][h*2+e] <-> physical class wn*64 + 16t + 2ni + e
        #pragma unroll
        for (int mi = 0; mi < 2; mi++) {
            #pragma unroll
            for (int h = 0; h < 2; h++) {
                const int pixel = wm * 32 + mi * 16 + h * 8 + g;
                const int4* lp = (const int4*)(labels +
                    (size_t)(pix0 + pixel) * M_CLS + wn * 64 + t * 16);
                int4 l0 = __ldg(lp);
                int4 l1 = __ldg(lp + 1);
                int4 l2 = __ldg(lp + 2);
                int4 l3 = __ldg(lp + 3);
                int l[16] = { l0.x, l0.y, l0.z, l0.w, l1.x, l1.y, l1.z, l1.w,
                              l2.x, l2.y, l2.z, l2.w, l3.x, l3.y, l3.z, l3.w };
                float sn = 0.0f, sp = 0.0f;
                #pragma unroll
                for (int ni = 0; ni < 8; ni++) {
                    #pragma unroll
                    for (int e = 0; e < 2; e++) {
                        int   lv = l[2 * ni + e];
                        float v  = acc[mi][ni][h * 2 + e] * INV_T;
                        float ev = __expf(lv ? -v : v);
                        if (lv) sp += ev; else sn += ev;
                    }
                }
                sn += __shfl_xor_sync(0xFFFFFFFFu, sn, 1);
                sn += __shfl_xor_sync(0xFFFFFFFFu, sn, 2);
                sp += __shfl_xor_sync(0xFFFFFFFFu, sp, 1);
                sp += __shfl_xor_sync(0xFFFFFFFFu, sp, 2);
                if (t == 0) {
                    red_sn[wn * 128 + pixel] = sn;
                    red_sp[wn * 128 + pixel] = sp;
                }
            }
        }
        __syncthreads();

        float th_loss = 0.0f, th_cnt = 0.0f;
        if (tid < 128) {
            float tsn = red_sn[tid] + red_sn[128 + tid] + red_sn[256 + tid] + red_sn[384 + tid];
            float tsp = red_sp[tid] + red_sp[128 + tid] + red_sp[256 + tid] + red_sp[384 + tid];
            float loss = logf(tsn * tsp + 1.0f);
            th_loss = loss;
            th_cnt  = (loss != 0.0f) ? 1.0f : 0.0f;
            #pragma unroll
            for (int o = 16; o > 0; o >>= 1) {
                th_loss += __shfl_xor_sync(0xFFFFFFFFu, th_loss, o);
                th_cnt  += __shfl_xor_sync(0xFFFFFFFFu, th_cnt,  o);
            }
            if (lane == 0) { wpart[warp] = th_loss; wpart[warp + 4] = th_cnt; }
        }
        __syncthreads();
        if (tid == 0) {
            acc_s += (double)(wpart[0] + wpart[1] + wpart[2] + wpart[3]);
            acc_c += wpart[4] + wpart[5] + wpart[6] + wpart[7];
        }

        fbase = fbase_next;
    }

    // ---- publish per-CTA totals; last CTA reduces ----
    __shared__ bool is_last;
    if (tid == 0) {
        g_sum[blockIdx.x] = acc_s;
        g_cnt[blockIdx.x] = acc_c;
        __threadfence();
        unsigned old = atomicAdd(&g_done, 1u);
        is_last = (old == GRID - 1);
    }
    __syncthreads();

    if (is_last) {
        __shared__ double dsum[GRID];
        __shared__ float  fcnt[GRID];
        if (tid < GRID) {
            dsum[tid] = g_sum[tid];
            fcnt[tid] = g_cnt[tid];
        }
        __syncthreads();
        if (tid == 0) {
            double s = 0.0;
            float  c = 0.0f;
            #pragma unroll 1
            for (int i = 0; i < GRID; i++) { s += dsum[i]; c += fcnt[i]; }
            out[0] = (c == 0.0f) ? 0.0f : (float)(s / (double)fmaxf(c, 1.0f));
            __threadfence();
            g_done = 0;   // reset for graph replay
        }
    }
}

extern "C" void kernel_launch(void* const* d_in, const int* in_sizes, int n_in,
                              void* d_out, int out_size)
{
    // metadata.txt order: feats (f32), queue (f32), labels (i32).
    // feats and labels have identical element counts — positional ID only.
    const float* feats  = (const float*)d_in[0];
    const float* queue  = (const float*)d_in[1];
    const int*   labels = (const int*)d_in[2];

    cudaFuncSetAttribute(pcl_persist_kernel,
                         cudaFuncAttributeMaxDynamicSharedMemorySize, SMEM_BYTES);

    queue_to_bf16_kernel<<<M_CLS * C_DIM / (2 * 256), 256>>>(queue);
    pcl_persist_kernel<<<GRID, NTHREADS, SMEM_BYTES>>>(feats, labels, (float*)d_out);
}